// round 12
// baseline (speedup 1.0000x reference)
#include <cuda_runtime.h>

// LSTM: B=32768, T=28, IN=28, H=8, gates i,j,f,o (cols 0-7,8-15,16-23,24-31).
// R12 = R11 + 2 ELEMENTS PER LANE (4 per warp). R11 evidence: per-warp step
// critical path ~500cyc (issue 48% with only 252 issues/SMSP-step) -> all
// warps in correlated dependency stalls; instruction count is NOT binding.
// Two independent recurrence chains per thread interleave: chain 1 issues
// inside chain 0's LDS/MUFU/SHFL stalls. Weights (72 regs) shared by both.

#define T_STEPS 28
#define IN_DIM 28
#define NH 8
#define NC 10
#define TPB 128
#define ELEMS_PER_CTA 16                      // 4 warps * 4 elems
#define X_FLOATS_PER_ELEM (T_STEPS * IN_DIM)  // 784
#define X_F4_PER_CTA (ELEMS_PER_CTA * X_FLOATS_PER_ELEM / 4)  // 3136

typedef unsigned long long u64;

__device__ __forceinline__ u64 pack2(float lo, float hi) {
    u64 r;
    asm("mov.b64 %0, {%1, %2};" : "=l"(r) : "f"(lo), "f"(hi));
    return r;
}
__device__ __forceinline__ void unpack2(u64 v, float& lo, float& hi) {
    asm("mov.b64 {%0, %1}, %2;" : "=f"(lo), "=f"(hi) : "l"(v));
}
__device__ __forceinline__ u64 fma2(u64 a, u64 b, u64 c) {
    u64 d;
    asm("fma.rn.f32x2 %0, %1, %2, %3;" : "=l"(d) : "l"(a), "l"(b), "l"(c));
    return d;
}
__device__ __forceinline__ float rcp_fast(float x) {
    float r;
    asm("rcp.approx.ftz.f32 %0, %1;" : "=f"(r) : "f"(x));
    return r;
}
__device__ __forceinline__ float ex2_fast(float x) {
    float r;
    asm("ex2.approx.ftz.f32 %0, %1;" : "=f"(r) : "f"(x));
    return r;
}

#define LOG2E 1.4426950408889634f

__device__ __forceinline__ float sigmoid_f(float x) {
    return rcp_fast(1.0f + ex2_fast(-x * LOG2E));
}
__device__ __forceinline__ float tanh_f(float x) {
    return 1.0f - 2.0f * rcp_fast(1.0f + ex2_fast(2.0f * LOG2E * x));
}

__global__ void __launch_bounds__(TPB, 3)   // 170-reg cap
lstm_kernel(const float* __restrict__ x,
            const float* __restrict__ W,     // [36, 32] row-major
            const float* __restrict__ b,     // [32]
            const float* __restrict__ ow,    // [8, 10]
            const float* __restrict__ ob,    // [10]
            float* __restrict__ out,         // [B, 10]
            int B)
{
    __shared__ __align__(16) float sX[ELEMS_PER_CTA * X_FLOATS_PER_ELEM];
    __shared__ __align__(16) float sH[ELEMS_PER_CTA * NH];   // h exchange

    const int tid = threadIdx.x;

    // ---- bulk-stage this CTA's x: 50KB, fully coalesced, deep MLP ----
    {
        const float4* __restrict__ gx = reinterpret_cast<const float4*>(
            x + (size_t)blockIdx.x * ELEMS_PER_CTA * X_FLOATS_PER_ELEM);
        float4* sx4 = reinterpret_cast<float4*>(sX);
#pragma unroll
        for (int i = 0; i < X_F4_PER_CTA / TPB; i++)          // 24 iters
            sx4[i * TPB + tid] = gx[i * TPB + tid];
        if (tid < X_F4_PER_CTA - (X_F4_PER_CTA / TPB) * TPB)  // 64 rem
            sx4[(X_F4_PER_CTA / TPB) * TPB + tid] =
                gx[(X_F4_PER_CTA / TPB) * TPB + tid];
    }

    const int lid = tid & 31;
    const int q   = lid & 15;                 // lane within half-warp
    // this thread's two elements (local): warp owns 4 consecutive elements
    const int el0 = (tid >> 5) * 4 + (lid >> 4);
    const int el1 = el0 + 2;
    const int elemg0 = blockIdx.x * ELEMS_PER_CTA + el0;
    const int elemg1 = blockIdx.x * ELEMS_PER_CTA + el1;

    // ---- weight column pair (q, q+16): 18 K-pairs each, in registers ----
    u64 wA[18], wB[18];
#pragma unroll
    for (int m = 0; m < 18; m++) {
        wA[m] = pack2(W[(2 * m) * 32 + q],      W[(2 * m + 1) * 32 + q]);
        wB[m] = pack2(W[(2 * m) * 32 + q + 16], W[(2 * m + 1) * 32 + q + 16]);
    }
    // bias seeds; FORGET_BIAS baked into f-column (q<8)
    const u64 accA0 = pack2(b[q], 0.0f);
    const u64 accB0 = pack2(b[q + 16] + (q < 8 ? 1.0f : 0.0f), 0.0f);

    // A-column activation select: q<8 -> sigmoid(i), q>=8 -> tanh(j)
    const bool ij = (q < 8);
    const float Ca = ij ? -LOG2E : 2.0f * LOG2E;
    const float Aa = ij ? 0.0f : 1.0f;
    const float Ba = ij ? 1.0f : -2.0f;

    __syncthreads();   // staging complete

    if (elemg0 >= B) return;

    const ulonglong2* __restrict__ xs0 = reinterpret_cast<const ulonglong2*>(
        sX + el0 * X_FLOATS_PER_ELEM);
    const ulonglong2* __restrict__ xs1 = reinterpret_cast<const ulonglong2*>(
        sX + el1 * X_FLOATS_PER_ELEM);
    const ulonglong2* __restrict__ hv0 = reinterpret_cast<const ulonglong2*>(
        sH + el0 * NH);
    const ulonglong2* __restrict__ hv1 = reinterpret_cast<const ulonglong2*>(
        sH + el1 * NH);

    // per-chain state
    ulonglong2 h01_0, h23_0, h01_1, h23_1;
    h01_0.x = h01_0.y = h23_0.x = h23_0.y = 0ull;
    h01_1.x = h01_1.y = h23_1.x = h23_1.y = 0ull;
    float c0 = 0.0f, c1 = 0.0f;

#pragma unroll 1
    for (int t = 0; t < T_STEPS; t++) {
        u64 aA0 = accA0, aB0 = accB0;
        u64 aA1 = accA0, aB1 = accB0;

        // interleaved x-FMA chains; loads grouped per pair to bound pressure
#pragma unroll
        for (int i = 0; i < 7; i++) {
            ulonglong2 xv0 = xs0[t * 7 + i];
            ulonglong2 xv1 = xs1[t * 7 + i];
            aA0 = fma2(xv0.x, wA[2 * i],     aA0);
            aB0 = fma2(xv0.x, wB[2 * i],     aB0);
            aA1 = fma2(xv1.x, wA[2 * i],     aA1);
            aB1 = fma2(xv1.x, wB[2 * i],     aB1);
            aA0 = fma2(xv0.y, wA[2 * i + 1], aA0);
            aB0 = fma2(xv0.y, wB[2 * i + 1], aB0);
            aA1 = fma2(xv1.y, wA[2 * i + 1], aA1);
            aB1 = fma2(xv1.y, wB[2 * i + 1], aB1);
        }
        // h contribution (pairs straight from prior LDS.128)
        aA0 = fma2(h01_0.x, wA[14], aA0); aB0 = fma2(h01_0.x, wB[14], aB0);
        aA1 = fma2(h01_1.x, wA[14], aA1); aB1 = fma2(h01_1.x, wB[14], aB1);
        aA0 = fma2(h01_0.y, wA[15], aA0); aB0 = fma2(h01_0.y, wB[15], aB0);
        aA1 = fma2(h01_1.y, wA[15], aA1); aB1 = fma2(h01_1.y, wB[15], aB1);
        aA0 = fma2(h23_0.x, wA[16], aA0); aB0 = fma2(h23_0.x, wB[16], aB0);
        aA1 = fma2(h23_1.x, wA[16], aA1); aB1 = fma2(h23_1.x, wB[16], aB1);
        aA0 = fma2(h23_0.y, wA[17], aA0); aB0 = fma2(h23_0.y, wB[17], aB0);
        aA1 = fma2(h23_1.y, wA[17], aA1); aB1 = fma2(h23_1.y, wB[17], aB1);

        // ---- chain-0 tail ----
        float alo, ahi, blo, bhi;
        unpack2(aA0, alo, ahi);
        unpack2(aB0, blo, bhi);
        float gA0 = alo + ahi, gB0 = blo + bhi;
        float actA_0 = Aa + Ba * rcp_fast(1.0f + ex2_fast(Ca * gA0));
        float actB_0 = sigmoid_f(gB0);
        // ---- chain-1 tail (independent, interleaves with chain 0) ----
        unpack2(aA1, alo, ahi);
        unpack2(aB1, blo, bhi);
        float gA1 = alo + ahi, gB1 = blo + bhi;
        float actA_1 = Aa + Ba * rcp_fast(1.0f + ex2_fast(Ca * gA1));
        float actB_1 = sigmoid_f(gB1);

        float pA0 = __shfl_down_sync(0xffffffffu, actA_0, 8, 16);
        float pB0 = __shfl_down_sync(0xffffffffu, actB_0, 8, 16);
        float pA1 = __shfl_down_sync(0xffffffffu, actA_1, 8, 16);
        float pB1 = __shfl_down_sync(0xffffffffu, actB_1, 8, 16);

        float cn0 = c0 * actB_0 + actA_0 * pA0;
        float cn1 = c1 * actB_1 + actA_1 * pA1;
        c0 = cn0;
        c1 = cn1;
        float h0 = tanh_f(cn0) * pB0;
        float h1 = tanh_f(cn1) * pB1;

        // h exchange via smem: owner lanes store both chains, reload packed
        if (q < 8) {
            sH[el0 * NH + q] = h0;
            sH[el1 * NH + q] = h1;
        }
        __syncwarp();
        h01_0 = hv0[0];  h23_0 = hv0[1];
        h01_1 = hv1[0];  h23_1 = hv1[1];
        __syncwarp();
    }

    // output projection: lane q (<10) computes class q for both elements
    if (q < NC) {
        float a0 = ob[q], a1 = a0;
        float lo, hi;
        unpack2(h01_0.x, lo, hi);
        a0 += lo * ow[0 * NC + q] + hi * ow[1 * NC + q];
        unpack2(h01_0.y, lo, hi);
        a0 += lo * ow[2 * NC + q] + hi * ow[3 * NC + q];
        unpack2(h23_0.x, lo, hi);
        a0 += lo * ow[4 * NC + q] + hi * ow[5 * NC + q];
        unpack2(h23_0.y, lo, hi);
        a0 += lo * ow[6 * NC + q] + hi * ow[7 * NC + q];

        unpack2(h01_1.x, lo, hi);
        a1 += lo * ow[0 * NC + q] + hi * ow[1 * NC + q];
        unpack2(h01_1.y, lo, hi);
        a1 += lo * ow[2 * NC + q] + hi * ow[3 * NC + q];
        unpack2(h23_1.x, lo, hi);
        a1 += lo * ow[4 * NC + q] + hi * ow[5 * NC + q];
        unpack2(h23_1.y, lo, hi);
        a1 += lo * ow[6 * NC + q] + hi * ow[7 * NC + q];

        out[(size_t)elemg0 * NC + q] = a0;
        if (elemg1 < B) out[(size_t)elemg1 * NC + q] = a1;
    }
}

extern "C" void kernel_launch(void* const* d_in, const int* in_sizes, int n_in,
                              void* d_out, int out_size) {
    const float* x  = (const float*)d_in[0];
    const float* W  = (const float*)d_in[1];
    const float* b  = (const float*)d_in[2];
    const float* ow = (const float*)d_in[3];
    const float* ob = (const float*)d_in[4];
    float* out = (float*)d_out;

    const int B = in_sizes[0] / (T_STEPS * IN_DIM);
    const int grid = (B + ELEMS_PER_CTA - 1) / ELEMS_PER_CTA;
    lstm_kernel<<<grid, TPB>>>(x, W, b, ow, ob, out, B);
}

// round 13
// speedup vs baseline: 1.0315x; 1.0315x over previous
#include <cuda_runtime.h>

// LSTM: B=32768, T=28, IN=28, H=8, gates i,j,f,o (cols 0-7,8-15,16-23,24-31).
// R13 = R11 (weights-in-registers, lane q owns gate-col pair (q,q+16), K-axis
// f32x2, 2 elems/warp, x staged in smem, h exchange via smem) with ALL
// activations moved to tanh.approx.f32 (1 MUFU) instead of ex2+rcp (2 MUFU,
// 44cyc serial). sigmoid(g)=0.5*tanh(0.5g)+0.5 with the 0.5 PRE-scale baked
// into the weight columns + bias (exact linear fold). Per-step MUFU 6 -> 3;
// R12 accounting showed MUFU queuing (~192cyc/660 window) + 3 serial 44cyc
// activation chains as the binding tail.

#define T_STEPS 28
#define IN_DIM 28
#define NH 8
#define NC 10
#define TPB 128
#define ELEMS_PER_CTA 8                       // 4 warps * 2 elems
#define X_FLOATS_PER_ELEM (T_STEPS * IN_DIM)  // 784
#define X_F4_PER_CTA (ELEMS_PER_CTA * X_FLOATS_PER_ELEM / 4)  // 1568

typedef unsigned long long u64;

__device__ __forceinline__ u64 pack2(float lo, float hi) {
    u64 r;
    asm("mov.b64 %0, {%1, %2};" : "=l"(r) : "f"(lo), "f"(hi));
    return r;
}
__device__ __forceinline__ void unpack2(u64 v, float& lo, float& hi) {
    asm("mov.b64 {%0, %1}, %2;" : "=f"(lo), "=f"(hi) : "l"(v));
}
__device__ __forceinline__ u64 fma2(u64 a, u64 b, u64 c) {
    u64 d;
    asm("fma.rn.f32x2 %0, %1, %2, %3;" : "=l"(d) : "l"(a), "l"(b), "l"(c));
    return d;
}
__device__ __forceinline__ float tanh_fast(float x) {
    float r;
    asm("tanh.approx.f32 %0, %1;" : "=f"(r) : "f"(x));
    return r;
}

__global__ void __launch_bounds__(TPB, 4)
lstm_kernel(const float* __restrict__ x,
            const float* __restrict__ W,     // [36, 32] row-major
            const float* __restrict__ b,     // [32]
            const float* __restrict__ ow,    // [8, 10]
            const float* __restrict__ ob,    // [10]
            float* __restrict__ out,         // [B, 10]
            int B)
{
    __shared__ __align__(16) float sX[ELEMS_PER_CTA * X_FLOATS_PER_ELEM];
    __shared__ __align__(16) float sH[ELEMS_PER_CTA * NH];   // h exchange

    const int tid = threadIdx.x;

    // ---- bulk-stage this CTA's x: 25KB, fully coalesced, deep MLP ----
    {
        const float4* __restrict__ gx = reinterpret_cast<const float4*>(
            x + (size_t)blockIdx.x * ELEMS_PER_CTA * X_FLOATS_PER_ELEM);
        float4* sx4 = reinterpret_cast<float4*>(sX);
#pragma unroll
        for (int i = 0; i < X_F4_PER_CTA / TPB; i++)
            sx4[i * TPB + tid] = gx[i * TPB + tid];
        if (tid < X_F4_PER_CTA - (X_F4_PER_CTA / TPB) * TPB)
            sx4[(X_F4_PER_CTA / TPB) * TPB + tid] =
                gx[(X_F4_PER_CTA / TPB) * TPB + tid];
    }

    const int lid  = tid & 31;
    const int q    = lid & 15;                 // lane within half-warp
    const int elem_local = (tid >> 5) * 2 + (lid >> 4);
    const int elem = blockIdx.x * ELEMS_PER_CTA + elem_local;

    // A-column: q<8 -> i-gate (sigmoid, prescale 0.5), q>=8 -> j-gate (tanh)
    // B-column: always sigmoid (f for q<8 incl. FORGET_BIAS, o for q>=8)
    const bool ij = (q < 8);
    const float sclA = ij ? 0.5f : 1.0f;       // pre-scale baked into column
    // post: act = Sa * t + Ta
    const float SaA = ij ? 0.5f : 1.0f;
    const float TaA = ij ? 0.5f : 0.0f;

    // ---- weight column pair (q, q+16): 18 K-pairs each, in registers ----
    // sigmoid columns stored PRE-SCALED by 0.5 (B always; A when q<8)
    u64 wA[18], wB[18];
#pragma unroll
    for (int m = 0; m < 18; m++) {
        wA[m] = pack2(sclA * W[(2 * m) * 32 + q],
                      sclA * W[(2 * m + 1) * 32 + q]);
        wB[m] = pack2(0.5f * W[(2 * m) * 32 + q + 16],
                      0.5f * W[(2 * m + 1) * 32 + q + 16]);
    }
    // bias seeds, same scaling; FORGET_BIAS baked into f-column (q<8)
    const u64 accA0 = pack2(sclA * b[q], 0.0f);
    const u64 accB0 = pack2(0.5f * (b[q + 16] + (ij ? 1.0f : 0.0f)), 0.0f);

    __syncthreads();   // staging complete

    if (elem >= B) return;

    const ulonglong2* __restrict__ xs = reinterpret_cast<const ulonglong2*>(
        sX + elem_local * X_FLOATS_PER_ELEM);
    const ulonglong2* __restrict__ hv = reinterpret_cast<const ulonglong2*>(
        sH + elem_local * NH);

    // h as 2 ulonglong2 = 4 packed pairs (h0,h1)..(h6,h7)
    ulonglong2 hp01, hp23;
    hp01.x = 0ull; hp01.y = 0ull; hp23.x = 0ull; hp23.y = 0ull;
    float c = 0.0f;                 // cell state (valid on lanes q<8)

#pragma unroll 1
    for (int t = 0; t < T_STEPS; t++) {
        // x from smem: 7 LDS.128 broadcast (2 distinct addrs/warp), lat 29
        ulonglong2 xv0 = xs[t * 7 + 0];
        ulonglong2 xv1 = xs[t * 7 + 1];
        ulonglong2 xv2 = xs[t * 7 + 2];
        ulonglong2 xv3 = xs[t * 7 + 3];
        ulonglong2 xv4 = xs[t * 7 + 4];
        ulonglong2 xv5 = xs[t * 7 + 5];
        ulonglong2 xv6 = xs[t * 7 + 6];

        u64 accA = accA0, accB = accB0;
        accA = fma2(xv0.x, wA[0],  accA); accB = fma2(xv0.x, wB[0],  accB);
        accA = fma2(xv0.y, wA[1],  accA); accB = fma2(xv0.y, wB[1],  accB);
        accA = fma2(xv1.x, wA[2],  accA); accB = fma2(xv1.x, wB[2],  accB);
        accA = fma2(xv1.y, wA[3],  accA); accB = fma2(xv1.y, wB[3],  accB);
        accA = fma2(xv2.x, wA[4],  accA); accB = fma2(xv2.x, wB[4],  accB);
        accA = fma2(xv2.y, wA[5],  accA); accB = fma2(xv2.y, wB[5],  accB);
        accA = fma2(xv3.x, wA[6],  accA); accB = fma2(xv3.x, wB[6],  accB);
        accA = fma2(xv3.y, wA[7],  accA); accB = fma2(xv3.y, wB[7],  accB);
        accA = fma2(xv4.x, wA[8],  accA); accB = fma2(xv4.x, wB[8],  accB);
        accA = fma2(xv4.y, wA[9],  accA); accB = fma2(xv4.y, wB[9],  accB);
        accA = fma2(xv5.x, wA[10], accA); accB = fma2(xv5.x, wB[10], accB);
        accA = fma2(xv5.y, wA[11], accA); accB = fma2(xv5.y, wB[11], accB);
        accA = fma2(xv6.x, wA[12], accA); accB = fma2(xv6.x, wB[12], accB);
        accA = fma2(xv6.y, wA[13], accA); accB = fma2(xv6.y, wB[13], accB);
        // h contribution last (pairs straight from LDS.128)
        accA = fma2(hp01.x, wA[14], accA); accB = fma2(hp01.x, wB[14], accB);
        accA = fma2(hp01.y, wA[15], accA); accB = fma2(hp01.y, wB[15], accB);
        accA = fma2(hp23.x, wA[16], accA); accB = fma2(hp23.x, wB[16], accB);
        accA = fma2(hp23.y, wA[17], accA); accB = fma2(hp23.y, wB[17], accB);

        // horizontal reduce: gate = lo + hi (pre-scaled where sigmoid)
        float alo, ahi, blo, bhi;
        unpack2(accA, alo, ahi);
        unpack2(accB, blo, bhi);
        float gA = alo + ahi;
        float gB = blo + bhi;

        // single-MUFU activations:
        //   A: q<8 sigmoid(i) = 0.5*tanh(g')+0.5 ; q>=8 tanh(j) = tanh(g)
        //   B: sigmoid = 0.5*tanh(g')+0.5
        float tA = tanh_fast(gA);
        float tB = tanh_fast(gB);
        float actA = fmaf(SaA, tA, TaA);
        float actB = fmaf(0.5f, tB, 0.5f);

        // lanes q<8 gather partner's (tanh(j), sig(o)) from lane q+8
        float pA = __shfl_down_sync(0xffffffffu, actA, 8, 16);
        float pB = __shfl_down_sync(0xffffffffu, actB, 8, 16);

        // state update (valid on q<8): is=actA, fs=actB, jt=pA, os=pB
        float cn = c * actB + actA * pA;
        c = cn;
        float h = tanh_fast(cn) * pB;

        // h exchange via smem: 8 owner lanes store, all lanes reload packed
        if (q < 8) sH[elem_local * NH + q] = h;
        __syncwarp();
        hp01 = hv[0];        // (h0,h1),(h2,h3)
        hp23 = hv[1];        // (h4,h5),(h6,h7)
        __syncwarp();        // reads done before next iter's stores
    }

    // output projection: lane q (<10) computes class q for its element
    if (q < NC) {
        float h0, h1, h2, h3, h4, h5, h6, h7;
        unpack2(hp01.x, h0, h1);
        unpack2(hp01.y, h2, h3);
        unpack2(hp23.x, h4, h5);
        unpack2(hp23.y, h6, h7);
        float a = ob[q];
        a += h0 * ow[0 * NC + q];
        a += h1 * ow[1 * NC + q];
        a += h2 * ow[2 * NC + q];
        a += h3 * ow[3 * NC + q];
        a += h4 * ow[4 * NC + q];
        a += h5 * ow[5 * NC + q];
        a += h6 * ow[6 * NC + q];
        a += h7 * ow[7 * NC + q];
        out[(size_t)elem * NC + q] = a;
    }
}

extern "C" void kernel_launch(void* const* d_in, const int* in_sizes, int n_in,
                              void* d_out, int out_size) {
    const float* x  = (const float*)d_in[0];
    const float* W  = (const float*)d_in[1];
    const float* b  = (const float*)d_in[2];
    const float* ow = (const float*)d_in[3];
    const float* ob = (const float*)d_in[4];
    float* out = (float*)d_out;

    const int B = in_sizes[0] / (T_STEPS * IN_DIM);
    const int grid = (B + ELEMS_PER_CTA - 1) / ELEMS_PER_CTA;
    lstm_kernel<<<grid, TPB>>>(x, W, b, ow, ob, out, B);
}

// round 14
// speedup vs baseline: 1.0797x; 1.0468x over previous
#include <cuda_runtime.h>

// LSTM: B=32768, T=28, IN=28, H=8, gates i,j,f,o (cols 0-7,8-15,16-23,24-31).
// R14: smem-PORT-bound fix (R9-13 all pinned at ~68us with L1=63% top pipe:
// 16 warps/SM x 9 LDS.128/step ~= 608 of 660 port-cyc/window). Go 4 elems
// per warp, 8 lanes/element: lane q owns ALL FOUR gates of hidden unit q
// (cols q, q+8, q+16, q+24; 4x18 K-packed f32x2 weight regs). x broadcast
// width 16->8 lanes halves x port traffic; SHFL eliminated (c_q/h_q local).
// sigmoid cols prescaled 0.5 (tanh.approx form). launch_bounds(128,2): 256
// reg cap for ~195 live regs, zero spill.

#define T_STEPS 28
#define IN_DIM 28
#define NH 8
#define NC 10
#define TPB 128
#define ELEMS_PER_CTA 16                      // 4 warps * 4 elems
#define X_FLOATS_PER_ELEM (T_STEPS * IN_DIM)  // 784
#define X_F4_PER_CTA (ELEMS_PER_CTA * X_FLOATS_PER_ELEM / 4)  // 3136

typedef unsigned long long u64;

__device__ __forceinline__ u64 pack2(float lo, float hi) {
    u64 r;
    asm("mov.b64 %0, {%1, %2};" : "=l"(r) : "f"(lo), "f"(hi));
    return r;
}
__device__ __forceinline__ void unpack2(u64 v, float& lo, float& hi) {
    asm("mov.b64 {%0, %1}, %2;" : "=f"(lo), "=f"(hi) : "l"(v));
}
__device__ __forceinline__ u64 fma2(u64 a, u64 b, u64 c) {
    u64 d;
    asm("fma.rn.f32x2 %0, %1, %2, %3;" : "=l"(d) : "l"(a), "l"(b), "l"(c));
    return d;
}
__device__ __forceinline__ float tanh_fast(float x) {
    float r;
    asm("tanh.approx.f32 %0, %1;" : "=f"(r) : "f"(x));
    return r;
}

__global__ void __launch_bounds__(TPB, 2)   // 256-reg cap: NO spill
lstm_kernel(const float* __restrict__ x,
            const float* __restrict__ W,     // [36, 32] row-major
            const float* __restrict__ b,     // [32]
            const float* __restrict__ ow,    // [8, 10]
            const float* __restrict__ ob,    // [10]
            float* __restrict__ out,         // [B, 10]
            int B)
{
    __shared__ __align__(16) float sX[ELEMS_PER_CTA * X_FLOATS_PER_ELEM];
    __shared__ __align__(16) float sH[ELEMS_PER_CTA * NH];   // h exchange

    const int tid = threadIdx.x;

    // ---- bulk-stage this CTA's x: 50KB, fully coalesced, deep MLP ----
    {
        const float4* __restrict__ gx = reinterpret_cast<const float4*>(
            x + (size_t)blockIdx.x * ELEMS_PER_CTA * X_FLOATS_PER_ELEM);
        float4* sx4 = reinterpret_cast<float4*>(sX);
#pragma unroll
        for (int i = 0; i < X_F4_PER_CTA / TPB; i++)          // 24 iters
            sx4[i * TPB + tid] = gx[i * TPB + tid];
        if (tid < X_F4_PER_CTA - (X_F4_PER_CTA / TPB) * TPB)  // 64 rem
            sx4[(X_F4_PER_CTA / TPB) * TPB + tid] =
                gx[(X_F4_PER_CTA / TPB) * TPB + tid];
    }

    const int lid = tid & 31;
    const int q   = lid & 7;                  // hidden unit this lane owns
    const int sub = lid >> 3;                 // element-in-warp 0..3
    const int elem_local = (tid >> 5) * 4 + sub;
    const int elem = blockIdx.x * ELEMS_PER_CTA + elem_local;

    // ---- 4 gate columns of hidden unit q, K-packed f32x2, in registers ----
    // i: col q (sigmoid, 0.5 prescale), j: col q+8 (tanh, no scale),
    // f: col q+16 (sigmoid+FORGET_BIAS), o: col q+24 (sigmoid)
    u64 wI[18], wJ[18], wF[18], wO[18];
#pragma unroll
    for (int m = 0; m < 18; m++) {
        wI[m] = pack2(0.5f * W[(2 * m) * 32 + q],
                      0.5f * W[(2 * m + 1) * 32 + q]);
        wJ[m] = pack2(W[(2 * m) * 32 + q + 8],
                      W[(2 * m + 1) * 32 + q + 8]);
        wF[m] = pack2(0.5f * W[(2 * m) * 32 + q + 16],
                      0.5f * W[(2 * m + 1) * 32 + q + 16]);
        wO[m] = pack2(0.5f * W[(2 * m) * 32 + q + 24],
                      0.5f * W[(2 * m + 1) * 32 + q + 24]);
    }
    const u64 aI0 = pack2(0.5f * b[q], 0.0f);
    const u64 aJ0 = pack2(b[q + 8], 0.0f);
    const u64 aF0 = pack2(0.5f * (b[q + 16] + 1.0f), 0.0f);  // FORGET_BIAS
    const u64 aO0 = pack2(0.5f * b[q + 24], 0.0f);

    __syncthreads();   // staging complete

    if (elem >= B) return;

    const ulonglong2* __restrict__ xs = reinterpret_cast<const ulonglong2*>(
        sX + elem_local * X_FLOATS_PER_ELEM);
    const ulonglong2* __restrict__ hv = reinterpret_cast<const ulonglong2*>(
        sH + elem_local * NH);

    u64 hk[4];                      // h as 4 packed pairs (h0,h1)..(h6,h7)
#pragma unroll
    for (int m = 0; m < 4; m++) hk[m] = 0ull;
    float c = 0.0f;

#pragma unroll 1
    for (int t = 0; t < T_STEPS; t++) {
        // x: 7 LDS.128, 8-lane broadcast groups (4 distinct addrs/warp)
        ulonglong2 xv[7];
#pragma unroll
        for (int i = 0; i < 7; i++) xv[i] = xs[t * 7 + i];

        u64 aI = aI0, aJ = aJ0, aF = aF0, aO = aO0;
        // x contribution: K-pairs 0..13 (4 independent 18-deep chains)
#pragma unroll
        for (int m = 0; m < 14; m++) {
            u64 xk = (m & 1) ? xv[m >> 1].y : xv[m >> 1].x;
            aI = fma2(xk, wI[m], aI);
            aJ = fma2(xk, wJ[m], aJ);
            aF = fma2(xk, wF[m], aF);
            aO = fma2(xk, wO[m], aO);
        }
        // h contribution: K-pairs 14..17
#pragma unroll
        for (int m = 0; m < 4; m++) {
            aI = fma2(hk[m], wI[14 + m], aI);
            aJ = fma2(hk[m], wJ[14 + m], aJ);
            aF = fma2(hk[m], wF[14 + m], aF);
            aO = fma2(hk[m], wO[14 + m], aO);
        }

        // horizontal reduce
        float lo, hi;
        unpack2(aI, lo, hi); float gi = lo + hi;
        unpack2(aJ, lo, hi); float gj = lo + hi;
        unpack2(aF, lo, hi); float gf = lo + hi;
        unpack2(aO, lo, hi); float go = lo + hi;

        // activations: sigmoid = 0.5*tanh(prescaled)+0.5 ; j,c = tanh
        float si = fmaf(0.5f, tanh_fast(gi), 0.5f);
        float tj = tanh_fast(gj);
        float sf = fmaf(0.5f, tanh_fast(gf), 0.5f);
        float so = fmaf(0.5f, tanh_fast(go), 0.5f);

        float cn = c * sf + si * tj;
        c = cn;
        float h = tanh_fast(cn) * so;

        // h exchange: ALL 32 lanes store (128B contiguous per warp),
        // reload packed pairs via 2 LDS.128
        sH[elem_local * NH + q] = h;
        __syncwarp();
        ulonglong2 h01 = hv[0];
        ulonglong2 h23 = hv[1];
        hk[0] = h01.x; hk[1] = h01.y; hk[2] = h23.x; hk[3] = h23.y;
        __syncwarp();        // reads done before next iter's stores
    }

    // output projection: 8 lanes per element; lane q does class q,
    // lanes 0,1 additionally do classes 8,9
    {
        float h0, h1, h2, h3, h4, h5, h6, h7;
        float lo, hi;
        unpack2(hk[0], lo, hi); h0 = lo; h1 = hi;
        unpack2(hk[1], lo, hi); h2 = lo; h3 = hi;
        unpack2(hk[2], lo, hi); h4 = lo; h5 = hi;
        unpack2(hk[3], lo, hi); h6 = lo; h7 = hi;

#pragma unroll
        for (int rep = 0; rep < 2; rep++) {
            int cls = (rep == 0) ? q : (8 + q);
            if (rep == 0 || q < 2) {
                float a = ob[cls];
                a += h0 * ow[0 * NC + cls];
                a += h1 * ow[1 * NC + cls];
                a += h2 * ow[2 * NC + cls];
                a += h3 * ow[3 * NC + cls];
                a += h4 * ow[4 * NC + cls];
                a += h5 * ow[5 * NC + cls];
                a += h6 * ow[6 * NC + cls];
                a += h7 * ow[7 * NC + cls];
                out[(size_t)elem * NC + cls] = a;
            }
        }
    }
}

extern "C" void kernel_launch(void* const* d_in, const int* in_sizes, int n_in,
                              void* d_out, int out_size) {
    const float* x  = (const float*)d_in[0];
    const float* W  = (const float*)d_in[1];
    const float* b  = (const float*)d_in[2];
    const float* ow = (const float*)d_in[3];
    const float* ob = (const float*)d_in[4];
    float* out = (float*)d_out;

    const int B = in_sizes[0] / (T_STEPS * IN_DIM);
    const int grid = (B + ELEMS_PER_CTA - 1) / ELEMS_PER_CTA;
    lstm_kernel<<<grid, TPB>>>(x, W, b, ow, ob, out, B);
}

// round 15
// speedup vs baseline: 1.1808x; 1.0936x over previous
#include <cuda_runtime.h>

// LSTM: B=32768, T=28, IN=28, H=8, gates i,j,f,o (cols 0-7,8-15,16-23,24-31).
// R15 = R14 (lane q owns all 4 gates of hidden unit q; 4x18 K-packed f32x2
// weight regs; 4 elems/warp; x staged in smem; tanh.approx activations with
// 0.5-prescaled sigmoid columns) + SOFTWARE PIPELINE: the x-part of step
// t+1's gates (56 fma2, independent of h) is computed during step t's
// h-tail, removing it from the recurrence critical path (R14: ~600cyc step
// window vs ~300 static; x-GEMM sat inside the serial h chain). Also
// double-buffered sH -> one syncwarp per step instead of two.

#define T_STEPS 28
#define IN_DIM 28
#define NH 8
#define NC 10
#define TPB 128
#define ELEMS_PER_CTA 16                      // 4 warps * 4 elems
#define X_FLOATS_PER_ELEM (T_STEPS * IN_DIM)  // 784
#define X_F4_PER_CTA (ELEMS_PER_CTA * X_FLOATS_PER_ELEM / 4)  // 3136

typedef unsigned long long u64;

__device__ __forceinline__ u64 pack2(float lo, float hi) {
    u64 r;
    asm("mov.b64 %0, {%1, %2};" : "=l"(r) : "f"(lo), "f"(hi));
    return r;
}
__device__ __forceinline__ void unpack2(u64 v, float& lo, float& hi) {
    asm("mov.b64 {%0, %1}, %2;" : "=f"(lo), "=f"(hi) : "l"(v));
}
__device__ __forceinline__ u64 fma2(u64 a, u64 b, u64 c) {
    u64 d;
    asm("fma.rn.f32x2 %0, %1, %2, %3;" : "=l"(d) : "l"(a), "l"(b), "l"(c));
    return d;
}
__device__ __forceinline__ float tanh_fast(float x) {
    float r;
    asm("tanh.approx.f32 %0, %1;" : "=f"(r) : "f"(x));
    return r;
}

__global__ void __launch_bounds__(TPB, 2)   // 256-reg cap: NO spill
lstm_kernel(const float* __restrict__ x,
            const float* __restrict__ W,     // [36, 32] row-major
            const float* __restrict__ b,     // [32]
            const float* __restrict__ ow,    // [8, 10]
            const float* __restrict__ ob,    // [10]
            float* __restrict__ out,         // [B, 10]
            int B)
{
    __shared__ __align__(16) float sX[ELEMS_PER_CTA * X_FLOATS_PER_ELEM];
    __shared__ __align__(16) float sH[2][ELEMS_PER_CTA * NH];  // dbl-buffered

    const int tid = threadIdx.x;

    // ---- bulk-stage this CTA's x: 50KB, fully coalesced, deep MLP ----
    {
        const float4* __restrict__ gx = reinterpret_cast<const float4*>(
            x + (size_t)blockIdx.x * ELEMS_PER_CTA * X_FLOATS_PER_ELEM);
        float4* sx4 = reinterpret_cast<float4*>(sX);
#pragma unroll
        for (int i = 0; i < X_F4_PER_CTA / TPB; i++)          // 24 iters
            sx4[i * TPB + tid] = gx[i * TPB + tid];
        if (tid < X_F4_PER_CTA - (X_F4_PER_CTA / TPB) * TPB)  // 64 rem
            sx4[(X_F4_PER_CTA / TPB) * TPB + tid] =
                gx[(X_F4_PER_CTA / TPB) * TPB + tid];
    }

    const int lid = tid & 31;
    const int q   = lid & 7;                  // hidden unit this lane owns
    const int sub = lid >> 3;                 // element-in-warp 0..3
    const int elem_local = (tid >> 5) * 4 + sub;
    const int elem = blockIdx.x * ELEMS_PER_CTA + elem_local;

    // ---- 4 gate columns of hidden unit q, K-packed f32x2, in registers ----
    u64 wI[18], wJ[18], wF[18], wO[18];
#pragma unroll
    for (int m = 0; m < 18; m++) {
        wI[m] = pack2(0.5f * W[(2 * m) * 32 + q],
                      0.5f * W[(2 * m + 1) * 32 + q]);
        wJ[m] = pack2(W[(2 * m) * 32 + q + 8],
                      W[(2 * m + 1) * 32 + q + 8]);
        wF[m] = pack2(0.5f * W[(2 * m) * 32 + q + 16],
                      0.5f * W[(2 * m + 1) * 32 + q + 16]);
        wO[m] = pack2(0.5f * W[(2 * m) * 32 + q + 24],
                      0.5f * W[(2 * m + 1) * 32 + q + 24]);
    }
    const u64 aI0 = pack2(0.5f * b[q], 0.0f);
    const u64 aJ0 = pack2(b[q + 8], 0.0f);
    const u64 aF0 = pack2(0.5f * (b[q + 16] + 1.0f), 0.0f);  // FORGET_BIAS
    const u64 aO0 = pack2(0.5f * b[q + 24], 0.0f);

    __syncthreads();   // staging complete

    if (elem >= B) return;

    const ulonglong2* __restrict__ xs = reinterpret_cast<const ulonglong2*>(
        sX + elem_local * X_FLOATS_PER_ELEM);

    u64 hk[4];                      // h as 4 packed pairs (h0,h1)..(h6,h7)
#pragma unroll
    for (int m = 0; m < 4; m++) hk[m] = 0ull;
    float c = 0.0f;

    // ---- prologue: x-part of step 0's gates ----
    u64 xI, xJ, xF, xO;
    {
        ulonglong2 xv[7];
#pragma unroll
        for (int i = 0; i < 7; i++) xv[i] = xs[i];
        xI = aI0; xJ = aJ0; xF = aF0; xO = aO0;
#pragma unroll
        for (int m = 0; m < 14; m++) {
            u64 xk = (m & 1) ? xv[m >> 1].y : xv[m >> 1].x;
            xI = fma2(xk, wI[m], xI);
            xJ = fma2(xk, wJ[m], xJ);
            xF = fma2(xk, wF[m], xF);
            xO = fma2(xk, wO[m], xO);
        }
    }

#pragma unroll 1
    for (int t = 0; t < T_STEPS; t++) {
        // full gates: h contribution onto the pipelined x-part
        u64 aI = xI, aJ = xJ, aF = xF, aO = xO;
#pragma unroll
        for (int m = 0; m < 4; m++) {
            aI = fma2(hk[m], wI[14 + m], aI);
            aJ = fma2(hk[m], wJ[14 + m], aJ);
            aF = fma2(hk[m], wF[14 + m], aF);
            aO = fma2(hk[m], wO[14 + m], aO);
        }

        // pipeline: x-part for t+1 (independent of h; fills tail stalls)
        {
            const int tn = (t < T_STEPS - 1) ? t + 1 : t;
            ulonglong2 xv[7];
#pragma unroll
            for (int i = 0; i < 7; i++) xv[i] = xs[tn * 7 + i];
            xI = aI0; xJ = aJ0; xF = aF0; xO = aO0;
#pragma unroll
            for (int m = 0; m < 14; m++) {
                u64 xk = (m & 1) ? xv[m >> 1].y : xv[m >> 1].x;
                xI = fma2(xk, wI[m], xI);
                xJ = fma2(xk, wJ[m], xJ);
                xF = fma2(xk, wF[m], xF);
                xO = fma2(xk, wO[m], xO);
            }
        }

        // tail: reduce, activations, state update
        float lo, hi;
        unpack2(aI, lo, hi); float gi = lo + hi;
        unpack2(aJ, lo, hi); float gj = lo + hi;
        unpack2(aF, lo, hi); float gf = lo + hi;
        unpack2(aO, lo, hi); float go = lo + hi;

        float si = fmaf(0.5f, tanh_fast(gi), 0.5f);
        float tj = tanh_fast(gj);
        float sf = fmaf(0.5f, tanh_fast(gf), 0.5f);
        float so = fmaf(0.5f, tanh_fast(go), 0.5f);

        float cn = c * sf + si * tj;
        c = cn;
        float h = tanh_fast(cn) * so;

        // h exchange: double-buffered -> single syncwarp per step
        float* sHb = sH[t & 1];
        sHb[elem_local * NH + q] = h;
        __syncwarp();
        const ulonglong2* hvb = reinterpret_cast<const ulonglong2*>(
            sHb + elem_local * NH);
        ulonglong2 h01 = hvb[0];
        ulonglong2 h23 = hvb[1];
        hk[0] = h01.x; hk[1] = h01.y; hk[2] = h23.x; hk[3] = h23.y;
    }

    // output projection: lane q does class q; lanes 0,1 also classes 8,9
    {
        float h0, h1, h2, h3, h4, h5, h6, h7;
        float lo, hi;
        unpack2(hk[0], lo, hi); h0 = lo; h1 = hi;
        unpack2(hk[1], lo, hi); h2 = lo; h3 = hi;
        unpack2(hk[2], lo, hi); h4 = lo; h5 = hi;
        unpack2(hk[3], lo, hi); h6 = lo; h7 = hi;

#pragma unroll
        for (int rep = 0; rep < 2; rep++) {
            int cls = (rep == 0) ? q : (8 + q);
            if (rep == 0 || q < 2) {
                float a = ob[cls];
                a += h0 * ow[0 * NC + cls];
                a += h1 * ow[1 * NC + cls];
                a += h2 * ow[2 * NC + cls];
                a += h3 * ow[3 * NC + cls];
                a += h4 * ow[4 * NC + cls];
                a += h5 * ow[5 * NC + cls];
                a += h6 * ow[6 * NC + cls];
                a += h7 * ow[7 * NC + cls];
                out[(size_t)elem * NC + cls] = a;
            }
        }
    }
}

extern "C" void kernel_launch(void* const* d_in, const int* in_sizes, int n_in,
                              void* d_out, int out_size) {
    const float* x  = (const float*)d_in[0];
    const float* W  = (const float*)d_in[1];
    const float* b  = (const float*)d_in[2];
    const float* ow = (const float*)d_in[3];
    const float* ob = (const float*)d_in[4];
    float* out = (float*)d_out;

    const int B = in_sizes[0] / (T_STEPS * IN_DIM);
    const int grid = (B + ELEMS_PER_CTA - 1) / ELEMS_PER_CTA;
    lstm_kernel<<<grid, TPB>>>(x, W, b, ow, ob, out, B);
}